// round 2
// baseline (speedup 1.0000x reference)
#include <cuda_runtime.h>
#include <cuda_bf16.h>

#define NVSEG 29000
#define HWSZ  (1024 * 1024)
#define BATCH 16
#define BHW   (BATCH * HWSZ)

// Scratch (__device__ globals are zero-initialized at module load).
// g_acc[v] = {sum_c0, sum_c1, sum_c2, count}. Invariant: zero at kernel_launch
// entry — replaced_kernel re-zeroes it after consuming, keeping every call
// (correctness run, capture, replays) identical.
__device__ float4 g_acc[NVSEG];
__device__ float4 g_rep[NVSEG];

// Pass 1: segment sums + counts. 8 pixels/thread, one float4 RED per pixel.
__global__ __launch_bounds__(256) void accumulate_kernel(
    const float* __restrict__ img, const int* __restrict__ seg)
{
    const long t = (long)blockIdx.x * blockDim.x + threadIdx.x;  // 0 .. BHW/8
    const long p = t << 3;
    const int  b = (int)(t >> 17);          // p >> 20
    const long rem = p & (HWSZ - 1);
    const float* base = img + (long)b * 3 * HWSZ + rem;

    // Front-batched loads (max MLP)
    const int4   s0 = *(const int4*)(seg + p);
    const int4   s1 = *(const int4*)(seg + p + 4);
    const float4 a0 = *(const float4*)(base + 0 * HWSZ);
    const float4 a1 = *(const float4*)(base + 0 * HWSZ + 4);
    const float4 b0 = *(const float4*)(base + 1 * HWSZ);
    const float4 b1 = *(const float4*)(base + 1 * HWSZ + 4);
    const float4 c0 = *(const float4*)(base + 2 * HWSZ);
    const float4 c1 = *(const float4*)(base + 2 * HWSZ + 4);

    atomicAdd(&g_acc[s0.x], make_float4(a0.x, b0.x, c0.x, 1.0f));
    atomicAdd(&g_acc[s0.y], make_float4(a0.y, b0.y, c0.y, 1.0f));
    atomicAdd(&g_acc[s0.z], make_float4(a0.z, b0.z, c0.z, 1.0f));
    atomicAdd(&g_acc[s0.w], make_float4(a0.w, b0.w, c0.w, 1.0f));
    atomicAdd(&g_acc[s1.x], make_float4(a1.x, b1.x, c1.x, 1.0f));
    atomicAdd(&g_acc[s1.y], make_float4(a1.y, b1.y, c1.y, 1.0f));
    atomicAdd(&g_acc[s1.z], make_float4(a1.z, b1.z, c1.z, 1.0f));
    atomicAdd(&g_acc[s1.w], make_float4(a1.w, b1.w, c1.w, 1.0f));
}

// Pass 2: rep[v] = fV[v] - sums[v]/max(cnt,1); then reset g_acc[v] = 0 so the
// next kernel_launch call starts from the zero invariant (saves a zero pass).
__global__ __launch_bounds__(256) void replaced_kernel(const float* __restrict__ fV) {
    int v = blockIdx.x * blockDim.x + threadIdx.x;
    if (v >= NVSEG) return;
    float4 a = g_acc[v];
    g_acc[v] = make_float4(0.f, 0.f, 0.f, 0.f);
    float inv = 1.0f / fmaxf(a.w, 1.0f);
    float4 r;
    r.x = fV[3 * v + 0] - a.x * inv;
    r.y = fV[3 * v + 1] - a.y * inv;
    r.z = fV[3 * v + 2] - a.z * inv;
    r.w = 0.f;
    g_rep[v] = r;
}

// Pass 3: out[p,c] = pixels[p,c] + rep[seg[p],c]. 8 px/thread, gathers first.
__global__ __launch_bounds__(256) void output_kernel(
    const float* __restrict__ img, const int* __restrict__ seg,
    float* __restrict__ out)
{
    const long t = (long)blockIdx.x * blockDim.x + threadIdx.x;
    const long p = t << 3;
    const int  b = (int)(t >> 17);
    const long rem = p & (HWSZ - 1);
    const float* base = img + (long)b * 3 * HWSZ + rem;

    const int4 s0 = *(const int4*)(seg + p);
    const int4 s1 = *(const int4*)(seg + p + 4);

    // Longest-latency first: 8 random gathers from the L2-resident table.
    float4 rr[8];
    rr[0] = g_rep[s0.x];  rr[1] = g_rep[s0.y];
    rr[2] = g_rep[s0.z];  rr[3] = g_rep[s0.w];
    rr[4] = g_rep[s1.x];  rr[5] = g_rep[s1.y];
    rr[6] = g_rep[s1.z];  rr[7] = g_rep[s1.w];

    float pa[8], pb[8], pc[8];
    *(float4*)(pa)     = *(const float4*)(base + 0 * HWSZ);
    *(float4*)(pa + 4) = *(const float4*)(base + 0 * HWSZ + 4);
    *(float4*)(pb)     = *(const float4*)(base + 1 * HWSZ);
    *(float4*)(pb + 4) = *(const float4*)(base + 1 * HWSZ + 4);
    *(float4*)(pc)     = *(const float4*)(base + 2 * HWSZ);
    *(float4*)(pc + 4) = *(const float4*)(base + 2 * HWSZ + 4);

    float o[24];
#pragma unroll
    for (int j = 0; j < 8; j++) {
        o[3 * j + 0] = pa[j] + rr[j].x;
        o[3 * j + 1] = pb[j] + rr[j].y;
        o[3 * j + 2] = pc[j] + rr[j].z;
    }

    float4* dst = (float4*)(out + p * 3);   // 24*t floats -> 16B aligned
#pragma unroll
    for (int k = 0; k < 6; k++) dst[k] = ((const float4*)o)[k];
}

extern "C" void kernel_launch(void* const* d_in, const int* in_sizes, int n_in,
                              void* d_out, int out_size)
{
    const float* img = (const float*)d_in[0];
    const int*   seg = (const int*)d_in[1];
    const float* fV  = (const float*)d_in[2];
    float* out = (float*)d_out;

    const int threads = 256;
    const int nvBlocks = (NVSEG + threads - 1) / threads;
    const int pixBlocks = (BHW / 8) / threads;   // 8192

    accumulate_kernel<<<pixBlocks, threads>>>(img, seg);
    replaced_kernel<<<nvBlocks, threads>>>(fV);
    output_kernel<<<pixBlocks, threads>>>(img, seg, out);
}

// round 3
// speedup vs baseline: 1.0704x; 1.0704x over previous
#include <cuda_runtime.h>
#include <cuda_bf16.h>

#define NVSEG 29000
#define HWSZ  (1024 * 1024)
#define BATCH 16
#define BHW   (BATCH * HWSZ)

// Scratch (__device__ globals are zero-initialized at module load).
// g_acc[v] = {sum_c0, sum_c1, sum_c2, count}. Invariant: zero at kernel_launch
// entry — replaced_kernel re-zeroes it after consuming, keeping every call
// (correctness run, capture, replays) identical.
__device__ float4 g_acc[NVSEG];
__device__ float4 g_rep[NVSEG];

// Pass 1: segment sums + counts. 4 pixels/thread, one float4 RED per pixel.
__global__ __launch_bounds__(256) void accumulate_kernel(
    const float* __restrict__ img, const int* __restrict__ seg)
{
    const long t = (long)blockIdx.x * blockDim.x + threadIdx.x;  // 0 .. BHW/4
    const long p = t << 2;
    const int  b = (int)(t >> 18);          // p >> 20
    const long rem = p & (HWSZ - 1);
    const float* base = img + (long)b * 3 * HWSZ + rem;

    const int4   s  = *(const int4*)(seg + p);
    const float4 c0 = *(const float4*)(base + 0 * HWSZ);
    const float4 c1 = *(const float4*)(base + 1 * HWSZ);
    const float4 c2 = *(const float4*)(base + 2 * HWSZ);

    atomicAdd(&g_acc[s.x], make_float4(c0.x, c1.x, c2.x, 1.0f));
    atomicAdd(&g_acc[s.y], make_float4(c0.y, c1.y, c2.y, 1.0f));
    atomicAdd(&g_acc[s.z], make_float4(c0.z, c1.z, c2.z, 1.0f));
    atomicAdd(&g_acc[s.w], make_float4(c0.w, c1.w, c2.w, 1.0f));
}

// Pass 2: rep[v] = fV[v] - sums[v]/max(cnt,1); then reset g_acc[v] = 0 so the
// next kernel_launch call starts from the zero invariant (saves a zero pass).
__global__ __launch_bounds__(256) void replaced_kernel(const float* __restrict__ fV) {
    int v = blockIdx.x * blockDim.x + threadIdx.x;
    if (v >= NVSEG) return;
    float4 a = g_acc[v];
    g_acc[v] = make_float4(0.f, 0.f, 0.f, 0.f);
    float inv = 1.0f / fmaxf(a.w, 1.0f);
    float4 r;
    r.x = fV[3 * v + 0] - a.x * inv;
    r.y = fV[3 * v + 1] - a.y * inv;
    r.z = fV[3 * v + 2] - a.z * inv;
    r.w = 0.f;
    g_rep[v] = r;
}

// Pass 3: out[p,c] = pixels[p,c] + rep[seg[p],c]. 4 px/thread.
// Gathers (the long pole: ~1 L1 wavefront per pixel) issued first.
__global__ __launch_bounds__(256) void output_kernel(
    const float* __restrict__ img, const int* __restrict__ seg,
    float* __restrict__ out)
{
    const long t = (long)blockIdx.x * blockDim.x + threadIdx.x;
    const long p = t << 2;
    const int  b = (int)(t >> 18);
    const long rem = p & (HWSZ - 1);
    const float* base = img + (long)b * 3 * HWSZ + rem;

    const int4 s = *(const int4*)(seg + p);

    const float4 r0 = g_rep[s.x];
    const float4 r1 = g_rep[s.y];
    const float4 r2 = g_rep[s.z];
    const float4 r3 = g_rep[s.w];

    const float4 c0 = *(const float4*)(base + 0 * HWSZ);
    const float4 c1 = *(const float4*)(base + 1 * HWSZ);
    const float4 c2 = *(const float4*)(base + 2 * HWSZ);

    // Interleave to [pixel, channel] row-major
    float4 o0, o1, o2;
    o0.x = c0.x + r0.x;  o0.y = c1.x + r0.y;  o0.z = c2.x + r0.z;  o0.w = c0.y + r1.x;
    o1.x = c1.y + r1.y;  o1.y = c2.y + r1.z;  o1.z = c0.z + r2.x;  o1.w = c1.z + r2.y;
    o2.x = c2.z + r2.z;  o2.y = c0.w + r3.x;  o2.z = c1.w + r3.y;  o2.w = c2.w + r3.z;

    float4* dst = (float4*)(out + p * 3);   // 12t floats -> 16B aligned
    dst[0] = o0;
    dst[1] = o1;
    dst[2] = o2;
}

extern "C" void kernel_launch(void* const* d_in, const int* in_sizes, int n_in,
                              void* d_out, int out_size)
{
    const float* img = (const float*)d_in[0];
    const int*   seg = (const int*)d_in[1];
    const float* fV  = (const float*)d_in[2];
    float* out = (float*)d_out;

    const int threads = 256;
    const int nvBlocks = (NVSEG + threads - 1) / threads;
    const int pixBlocks = (BHW / 4) / threads;   // 16384

    accumulate_kernel<<<pixBlocks, threads>>>(img, seg);
    replaced_kernel<<<nvBlocks, threads>>>(fV);
    output_kernel<<<pixBlocks, threads>>>(img, seg, out);
}